// round 1
// baseline (speedup 1.0000x reference)
#include <cuda_runtime.h>
#include <math.h>

#define HH 240
#define WW 320
#define HWPIX (HH * WW)
#define NC 10
#define K3_BLOCKS 300   // 300 * 256 == 76800 == HWPIX exactly

// ---------------- scratch (static device globals; no allocation) -------------
__device__ int                g_count[NC];                 // mask pixel count per class
__device__ unsigned long long g_best[NC];                  // (count<<32) | (~bin) argmax key
__device__ uint2              g_pix[NC][HWPIX];            // packed (x | y<<16), slope bits
__device__ int                g_pcnt[NC][K3_BLOCKS];       // inlier count partials
__device__ float              g_pdsum[NC][K3_BLOCKS];      // depth sum partials

// ---------------- K0: reset per-launch scratch (graph replays!) --------------
__global__ void k0_reset() {
    int t = threadIdx.x;
    if (t < NC) { g_count[t] = 0; g_best[t] = 0ULL; }
}

// ---------------- K1: compact masked pixels per class ------------------------
__global__ void k1_build(const int* __restrict__ label, const float* __restrict__ cm) {
    int p = blockIdx.x * blockDim.x + threadIdx.x;
    if (p >= HWPIX) return;
    int lab = label[p];
    if (lab < 1 || lab > NC) return;
    int c   = lab - 1;
    int pos = atomicAdd(&g_count[c], 1);
    int x = p % WW, y = p / WW;
    float dirx  = cm[(3 * c + 0) * HWPIX + p];
    float diry  = cm[(3 * c + 1) * HWPIX + p];
    float slope = __fdiv_rn(diry, dirx);        // matches jnp c3[1]/c3[0]
    uint2 e;
    e.x = (unsigned)(x | (y << 16));
    e.y = __float_as_uint(slope);
    g_pix[c][pos] = e;
}

// ---------------- K2: Hough vote, one CTA per (class, column) ----------------
// bin = y_idx*W + col ; per-column 240-bin shared histogram.
__global__ __launch_bounds__(256) void k2_vote() {
    __shared__ unsigned int       hist[HH];
    __shared__ unsigned long long red[256];

    const int col = blockIdx.x;
    const int c   = blockIdx.y;
    const int t   = threadIdx.x;

    if (t < HH) hist[t] = 0u;
    __syncthreads();

    const int   n    = g_count[c];
    const float xcol = (float)col;
    const uint2* __restrict__ pix = g_pix[c];

    for (int i = t; i < n; i += 256) {
        uint2 e     = pix[i];
        float xf    = (float)(e.x & 0xFFFFu);
        float yf    = (float)(e.x >> 16);
        float slope = __uint_as_float(e.y);
        // EXACT non-fused arithmetic to mirror jnp: round(y + slope*(x' - x))
        float d  = __fadd_rn(xcol, -xf);
        float tm = __fmul_rn(slope, d);
        float yv = __fadd_rn(yf, tm);
        float r  = rintf(yv);                    // round-half-even, like jnp.round
        if (r >= 0.0f && r <= (float)(HH - 1)) {
            atomicAdd(&hist[(int)r], 1u);
        }
    }
    __syncthreads();

    // per-block argmax key: max count, tie -> lowest flat bin index
    unsigned long long key = 0ULL;
    if (t < HH) {
        unsigned bin = (unsigned)(t * WW + col);
        key = ((unsigned long long)hist[t] << 32) |
              (unsigned long long)(0xFFFFFFFFu - bin);
    }
    red[t] = key;
    __syncthreads();
    #pragma unroll
    for (int s = 128; s > 0; s >>= 1) {
        if (t < s) { if (red[t + s] > red[t]) red[t] = red[t + s]; }
        __syncthreads();
    }
    if (t == 0) atomicMax(&g_best[c], red[0]);
}

// ---------------- K3: inlier count + depth sum (deterministic partials) ------
__global__ __launch_bounds__(256) void k3_inlier(const int* __restrict__ label,
                                                 const float* __restrict__ cm) {
    const int c = blockIdx.y;
    const int t = threadIdx.x;
    const int p = blockIdx.x * 256 + t;

    unsigned long long best = g_best[c];
    unsigned bin = 0xFFFFFFFFu - (unsigned)(best & 0xFFFFFFFFu);
    float cx = (float)(bin % WW);
    float cy = (float)(bin / WW);

    int   my = 0;
    float ds = 0.0f;
    if (p < HWPIX && label[p] == c + 1) {
        float dirx  = cm[(3 * c + 0) * HWPIX + p];
        float diry  = cm[(3 * c + 1) * HWPIX + p];
        float depth = cm[(3 * c + 2) * HWPIX + p];
        float xf = (float)(p % WW), yf = (float)(p / WW);
        float disx = xf - cx, disy = yf - cy;
        float dn  = sqrtf(disx * disx + disy * disy);   // 0 at center -> NaN dot -> excluded (matches ref)
        float dot = fabsf(disx / dn * dirx + disy / dn * diry);
        if (dot >= 0.9f) { my = 1; ds = depth; }
    }

    __shared__ int   scnt[256];
    __shared__ float ssum[256];
    scnt[t] = my; ssum[t] = ds;
    __syncthreads();
    #pragma unroll
    for (int s = 128; s > 0; s >>= 1) {
        if (t < s) { scnt[t] += scnt[t + s]; ssum[t] += ssum[t + s]; }
        __syncthreads();
    }
    if (t == 0) {
        g_pcnt[c][blockIdx.x]  = scnt[0];
        g_pdsum[c][blockIdx.x] = ssum[0];
    }
}

// ---------------- K4: finalize outputs ---------------------------------------
__global__ __launch_bounds__(256) void k4_final(float* __restrict__ out) {
    const int c = blockIdx.x;
    const int t = threadIdx.x;
    __shared__ int   scnt[256];
    __shared__ float ssum[256];

    int   a = 0; float s = 0.0f;
    for (int i = t; i < K3_BLOCKS; i += 256) { a += g_pcnt[c][i]; s += g_pdsum[c][i]; }
    scnt[t] = a; ssum[t] = s;
    __syncthreads();
    #pragma unroll
    for (int st = 128; st > 0; st >>= 1) {
        if (t < st) { scnt[t] += scnt[t + st]; ssum[t] += ssum[t + st]; }
        __syncthreads();
    }
    if (t == 0) {
        unsigned long long best = g_best[c];
        unsigned cntBest = (unsigned)(best >> 32);          // inlier_num (hist peak)
        unsigned bin     = 0xFFFFFFFFu - (unsigned)best;    // argmax flat bin
        float cx = (float)(bin % WW);
        float cy = (float)(bin / WW);
        bool trig = (g_count[c] >= 500) && (cntBest > 500u);
        int   icnt = scnt[0];
        float dsum = ssum[0];
        float dmean = (icnt > 0) ? (dsum / (float)icnt) : __int_as_float(0x7fc00000);
        out[c * 2 + 0]   = trig ? cx    : 0.0f;   // centers (1,10,2)
        out[c * 2 + 1]   = trig ? cy    : 0.0f;
        out[2 * NC + c]  = trig ? dmean : 0.0f;   // depths (1,10)
    }
}

// ---------------- launch ------------------------------------------------------
extern "C" void kernel_launch(void* const* d_in, const int* in_sizes, int n_in,
                              void* d_out, int out_size) {
    const int*   label;
    const float* cm;
    if (in_sizes[0] == HWPIX) {   // label first (int32, 76800 elems)
        label = (const int*)d_in[0];
        cm    = (const float*)d_in[1];
    } else {                      // swapped order
        label = (const int*)d_in[1];
        cm    = (const float*)d_in[0];
    }
    float* out = (float*)d_out;

    k0_reset <<<1, 32>>>();
    k1_build <<<(HWPIX + 255) / 256, 256>>>(label, cm);
    k2_vote  <<<dim3(WW, NC), 256>>>();
    k3_inlier<<<dim3(K3_BLOCKS, NC), 256>>>(label, cm);
    k4_final <<<NC, 256>>>(out);
}

// round 2
// speedup vs baseline: 1.5606x; 1.5606x over previous
#include <cuda_runtime.h>
#include <math.h>

#define HH 240
#define WW 320
#define HWPIX (HH * WW)
#define NC 10
#define NCOL 8                         // columns per vote CTA
#define NBLK 300                       // 300 * 256 == 76800 == HWPIX exactly

// ---------------- scratch (static device globals; zero at load) --------------
// Reset discipline: the finalize step of k3_final zeroes everything it and the
// earlier kernels consumed, so every launch (first call included) starts from
// zeroed scratch. No separate reset kernel.
__device__ int                g_count[NC];        // mask pixel count per class
__device__ unsigned long long g_best[NC];         // (count<<32) | ~bin argmax key
__device__ int                g_icnt[NC];         // inlier count accumulator
__device__ float              g_dsum[NC];         // depth sum accumulator
__device__ unsigned           g_done;             // last-block-done counter
__device__ uint2              g_pix[NC][HWPIX];   // packed (x | y<<16), slope bits

// ---------------- K1: compact masked pixels per class ------------------------
__global__ __launch_bounds__(256) void k1_build(const int* __restrict__ label,
                                                const float* __restrict__ cm) {
    __shared__ int s_cnt[NC], s_base[NC];
    const int t = threadIdx.x;
    if (t < NC) s_cnt[t] = 0;
    __syncthreads();

    const int p   = blockIdx.x * 256 + t;          // grid covers HWPIX exactly
    const int lab = label[p];
    int c = -1, pos = 0;
    if (lab >= 1 && lab <= NC) {
        c   = lab - 1;
        pos = atomicAdd(&s_cnt[c], 1);             // shared: cheap
    }
    __syncthreads();
    if (t < NC) s_base[t] = atomicAdd(&g_count[t], s_cnt[t]);  // 10 global/block
    __syncthreads();

    if (c >= 0) {
        const float dirx = cm[(3 * c + 0) * HWPIX + p];
        const float diry = cm[(3 * c + 1) * HWPIX + p];
        uint2 e;
        e.x = (unsigned)((p % WW) | ((p / WW) << 16));
        e.y = __float_as_uint(__fdiv_rn(diry, dirx));   // matches jnp c3[1]/c3[0]
        g_pix[c][s_base[c] + pos] = e;
    }
}

// ---------------- K2: Hough vote, one CTA per (class, 8-column group) --------
__global__ __launch_bounds__(256) void k2_vote() {
    __shared__ unsigned int       hist[NCOL][HH];   // 7680 B
    __shared__ unsigned long long red[256];

    const int c       = blockIdx.y;
    const int colbase = blockIdx.x * NCOL;
    const int t       = threadIdx.x;

    for (int i = t; i < NCOL * HH; i += 256) ((unsigned*)hist)[i] = 0u;
    __syncthreads();

    const int n = g_count[c];
    const uint2* __restrict__ pix = g_pix[c];

    for (int i = t; i < n; i += 256) {
        const uint2 e     = pix[i];
        const float xf    = (float)(e.x & 0xFFFFu);
        const float yf    = (float)(e.x >> 16);
        const float slope = __uint_as_float(e.y);
        #pragma unroll
        for (int j = 0; j < NCOL; j++) {
            // EXACT non-fused arithmetic mirroring jnp: round(y + slope*(x'-x))
            const float d  = __fadd_rn((float)(colbase + j), -xf);
            const float m  = __fmul_rn(slope, d);
            const float yv = __fadd_rn(yf, m);
            const float r  = rintf(yv);             // round-half-even, like jnp.round
            if (r >= 0.0f && r <= (float)(HH - 1)) {
                atomicAdd(&hist[j][(int)r], 1u);
            }
        }
    }
    __syncthreads();

    // block argmax: max count, tie -> lowest flat bin index
    unsigned long long key = 0ULL;
    for (int i = t; i < NCOL * HH; i += 256) {
        const int j = i / HH, row = i % HH;
        const unsigned cnt = hist[j][row];
        const unsigned bin = (unsigned)(row * WW + (colbase + j));
        const unsigned long long k =
            ((unsigned long long)cnt << 32) | (unsigned long long)(0xFFFFFFFFu - bin);
        if (k > key) key = k;
    }
    red[t] = key;
    __syncthreads();
    #pragma unroll
    for (int s = 128; s > 0; s >>= 1) {
        if (t < s) { if (red[t + s] > red[t]) red[t] = red[t + s]; }
        __syncthreads();
    }
    if (t == 0) atomicMax(&g_best[c], red[0]);
}

// ---------------- K3: inlier + depth (one thread per pixel) + finalize -------
__global__ __launch_bounds__(256) void k3_final(const int* __restrict__ label,
                                                const float* __restrict__ cm,
                                                float* __restrict__ out) {
    __shared__ int   scnt[NC];
    __shared__ float ssum[NC];
    __shared__ bool  s_last;
    const int t = threadIdx.x;
    if (t < NC) { scnt[t] = 0; ssum[t] = 0.0f; }
    __syncthreads();

    const int p   = blockIdx.x * 256 + t;
    const int lab = label[p];
    if (lab >= 1 && lab <= NC) {
        const int c = lab - 1;
        const unsigned long long best = g_best[c];
        const unsigned bin = 0xFFFFFFFFu - (unsigned)best;
        const float cx = (float)(bin % WW);
        const float cy = (float)(bin / WW);
        const float dirx = cm[(3 * c + 0) * HWPIX + p];
        const float diry = cm[(3 * c + 1) * HWPIX + p];
        const float xf = (float)(p % WW), yf = (float)(p / WW);
        const float disx = xf - cx, disy = yf - cy;
        const float dn  = sqrtf(disx * disx + disy * disy); // 0 at center -> NaN dot -> excluded
        const float dot = fabsf(disx / dn * dirx + disy / dn * diry);
        if (dot >= 0.9f) {
            atomicAdd(&scnt[c], 1);
            atomicAdd(&ssum[c], cm[(3 * c + 2) * HWPIX + p]);
        }
    }
    __syncthreads();

    if (t < NC && scnt[t] > 0) {
        atomicAdd(&g_icnt[t], scnt[t]);
        atomicAdd(&g_dsum[t], ssum[t]);
    }
    __threadfence();
    if (t == 0) s_last = (atomicAdd(&g_done, 1u) == (unsigned)(NBLK - 1));
    __syncthreads();

    if (s_last) {
        __threadfence();
        if (t < NC) {
            const int c = t;
            const unsigned long long best = g_best[c];
            const unsigned cntBest = (unsigned)(best >> 32);
            const unsigned bin     = 0xFFFFFFFFu - (unsigned)best;
            const float cx = (float)(bin % WW);
            const float cy = (float)(bin / WW);
            const bool trig = (g_count[c] >= 500) && (cntBest > 500u);
            const int   icnt = g_icnt[c];
            const float dsum = g_dsum[c];
            const float dmean = (icnt > 0) ? (dsum / (float)icnt)
                                           : __int_as_float(0x7fc00000);
            out[c * 2 + 0]  = trig ? cx    : 0.0f;   // centers (1,10,2)
            out[c * 2 + 1]  = trig ? cy    : 0.0f;
            out[2 * NC + c] = trig ? dmean : 0.0f;   // depths (1,10)
            // reset scratch for the next (graph-replayed) launch
            g_icnt[c]  = 0;
            g_dsum[c]  = 0.0f;
            g_count[c] = 0;
            g_best[c]  = 0ULL;
        }
        if (t == 0) g_done = 0u;
    }
}

// ---------------- launch ------------------------------------------------------
extern "C" void kernel_launch(void* const* d_in, const int* in_sizes, int n_in,
                              void* d_out, int out_size) {
    const int*   label;
    const float* cm;
    if (in_sizes[0] == HWPIX) {   // label first (int32, 76800 elems)
        label = (const int*)d_in[0];
        cm    = (const float*)d_in[1];
    } else {
        label = (const int*)d_in[1];
        cm    = (const float*)d_in[0];
    }
    float* out = (float*)d_out;

    k1_build<<<NBLK, 256>>>(label, cm);
    k2_vote <<<dim3(WW / NCOL, NC), 256>>>();
    k3_final<<<NBLK, 256>>>(label, cm, out);
}

// round 4
// speedup vs baseline: 1.9162x; 1.2279x over previous
#include <cuda_runtime.h>
#include <math.h>

#define HH 240
#define WW 320
#define HWPIX (HH * WW)
#define NC 10
#define NCOL 8                         // columns per vote CTA
#define NBLK 300                       // 300 * 256 == 76800 == HWPIX exactly

// ---- packed f32x2 helpers (sm_103a) -----------------------------------------
#define PK2(out, lo, hi) \
    asm("mov.b64 %0, {%1, %2};" : "=l"(out) : "f"(lo), "f"(hi))
#define UPK2(lo, hi, in) \
    asm("mov.b64 {%0, %1}, %2;" : "=f"(lo), "=f"(hi) : "l"(in))
#define MUL2(out, a, b) \
    asm("mul.rn.f32x2 %0, %1, %2;" : "=l"(out) : "l"(a), "l"(b))
#define ADD2(out, a, b) \
    asm("add.rn.f32x2 %0, %1, %2;" : "=l"(out) : "l"(a), "l"(b))

// ---------------- scratch (static device globals; zero at load) --------------
// The finalize step of k3_final re-zeroes everything consumed, so every launch
// (graph replays included) starts from zeroed scratch.
__device__ int                g_count[NC];
__device__ unsigned long long g_best[NC];
__device__ int                g_icnt[NC];
__device__ float              g_dsum[NC];
__device__ unsigned           g_done;
__device__ uint2              g_pix[NC][HWPIX];   // (x | y<<16), slope bits

// ---------------- K1: compact masked pixels per class ------------------------
__global__ __launch_bounds__(256) void k1_build(const int* __restrict__ label,
                                                const float* __restrict__ cm) {
    __shared__ int s_cnt[NC], s_base[NC];
    const int t = threadIdx.x;
    if (t < NC) s_cnt[t] = 0;
    __syncthreads();

    const int p   = blockIdx.x * 256 + t;
    const int lab = label[p];
    int c = -1, pos = 0;
    if (lab >= 1 && lab <= NC) {
        c   = lab - 1;
        pos = atomicAdd(&s_cnt[c], 1);
    }
    __syncthreads();
    if (t < NC) s_base[t] = atomicAdd(&g_count[t], s_cnt[t]);
    __syncthreads();

    if (c >= 0) {
        const float dirx = cm[(3 * c + 0) * HWPIX + p];
        const float diry = cm[(3 * c + 1) * HWPIX + p];
        uint2 e;
        e.x = (unsigned)((p % WW) | ((p / WW) << 16));
        e.y = __float_as_uint(__fdiv_rn(diry, dirx));   // jnp c3[1]/c3[0]
        g_pix[c][s_base[c] + pos] = e;
    }
}

// ---------------- K2: Hough vote ---------------------------------------------
// One CTA per (class, 8-column group). yv_j = y + slope*(col_j - x) computed
// with IEEE-rn packed f32x2 ops == bit-identical to scalar __fmul_rn/__fadd_rn.
__device__ __forceinline__ void vote_pixel(unsigned exy, unsigned sbits,
                                           int colbase, unsigned* hist,
                                           unsigned long long two2) {
    const int   xi = (int)(exy & 0xFFFFu);
    const float yf = (float)(exy >> 16);
    const float s  = __uint_as_float(sbits);

    // d_j = col_j - x are exact small integers in f32
    const float d0 = (float)(colbase - xi);
    unsigned long long s2, y2, dp, m, yv0, yv1, yv2, yv3;
    PK2(s2, s, s);
    PK2(y2, yf, yf);
    PK2(dp, d0, d0 + 1.0f);

    MUL2(m, s2, dp);  ADD2(yv0, y2, m);
    ADD2(dp, dp, two2);
    MUL2(m, s2, dp);  ADD2(yv1, y2, m);
    ADD2(dp, dp, two2);
    MUL2(m, s2, dp);  ADD2(yv2, y2, m);
    ADD2(dp, dp, two2);
    MUL2(m, s2, dp);  ADD2(yv3, y2, m);

    float f0, f1, f2, f3, f4, f5, f6, f7;
    UPK2(f0, f1, yv0);
    UPK2(f2, f3, yv1);
    UPK2(f4, f5, yv2);
    UPK2(f6, f7, yv3);

    // monotone in column -> endpoints bound the window; conservative skip
    const float mn = fminf(f0, f7), mx = fmaxf(f0, f7);
    if (mx < -0.5f || mn > 239.5f) return;

    int r;
    r = __float2int_rn(f0); if ((unsigned)r < (unsigned)HH) atomicAdd(&hist[0 * HH + r], 1u);
    r = __float2int_rn(f1); if ((unsigned)r < (unsigned)HH) atomicAdd(&hist[1 * HH + r], 1u);
    r = __float2int_rn(f2); if ((unsigned)r < (unsigned)HH) atomicAdd(&hist[2 * HH + r], 1u);
    r = __float2int_rn(f3); if ((unsigned)r < (unsigned)HH) atomicAdd(&hist[3 * HH + r], 1u);
    r = __float2int_rn(f4); if ((unsigned)r < (unsigned)HH) atomicAdd(&hist[4 * HH + r], 1u);
    r = __float2int_rn(f5); if ((unsigned)r < (unsigned)HH) atomicAdd(&hist[5 * HH + r], 1u);
    r = __float2int_rn(f6); if ((unsigned)r < (unsigned)HH) atomicAdd(&hist[6 * HH + r], 1u);
    r = __float2int_rn(f7); if ((unsigned)r < (unsigned)HH) atomicAdd(&hist[7 * HH + r], 1u);
}

__global__ __launch_bounds__(256) void k2_vote() {
    __shared__ unsigned int       hist[NCOL * HH];   // 7680 B
    __shared__ unsigned long long red[256];

    const int c       = blockIdx.y;
    const int colbase = blockIdx.x * NCOL;
    const int t       = threadIdx.x;

    for (int i = t; i < NCOL * HH; i += 256) hist[i] = 0u;
    __syncthreads();

    unsigned long long two2;
    PK2(two2, 2.0f, 2.0f);

    const int n  = g_count[c];
    const int n2 = n >> 1;
    const uint4* __restrict__ pix4 = (const uint4*)g_pix[c];

    for (int i = t; i < n2; i += 256) {
        const uint4 e = pix4[i];
        vote_pixel(e.x, e.y, colbase, hist, two2);
        vote_pixel(e.z, e.w, colbase, hist, two2);
    }
    if ((n & 1) && t == 0) {
        const uint2 e = g_pix[c][n - 1];
        vote_pixel(e.x, e.y, colbase, hist, two2);
    }
    __syncthreads();

    // block argmax: max count, tie -> lowest flat bin index
    unsigned long long key = 0ULL;
    for (int i = t; i < NCOL * HH; i += 256) {
        const int j = i / HH, row = i % HH;
        const unsigned bin = (unsigned)(row * WW + (colbase + j));
        const unsigned long long k =
            ((unsigned long long)hist[i] << 32) | (unsigned long long)(0xFFFFFFFFu - bin);
        if (k > key) key = k;
    }
    red[t] = key;
    __syncthreads();
    #pragma unroll
    for (int s = 128; s > 0; s >>= 1) {
        if (t < s) { if (red[t + s] > red[t]) red[t] = red[t + s]; }
        __syncthreads();
    }
    if (t == 0) atomicMax(&g_best[c], red[0]);
}

// ---------------- K3: inlier + depth (one thread per pixel) + finalize -------
__global__ __launch_bounds__(256) void k3_final(const int* __restrict__ label,
                                                const float* __restrict__ cm,
                                                float* __restrict__ out) {
    __shared__ int   scnt[NC];
    __shared__ float ssum[NC];
    __shared__ bool  s_last;
    const int t = threadIdx.x;
    if (t < NC) { scnt[t] = 0; ssum[t] = 0.0f; }
    __syncthreads();

    const int p   = blockIdx.x * 256 + t;
    const int lab = label[p];
    if (lab >= 1 && lab <= NC) {
        const int c = lab - 1;
        const unsigned long long best = g_best[c];
        const unsigned bin = 0xFFFFFFFFu - (unsigned)best;
        const float cx = (float)(bin % WW);
        const float cy = (float)(bin / WW);
        const float dirx = cm[(3 * c + 0) * HWPIX + p];
        const float diry = cm[(3 * c + 1) * HWPIX + p];
        const float xf = (float)(p % WW), yf = (float)(p / WW);
        const float disx = xf - cx, disy = yf - cy;
        const float dn  = sqrtf(disx * disx + disy * disy); // 0 at center -> NaN -> excluded
        const float dot = fabsf(disx / dn * dirx + disy / dn * diry);
        if (dot >= 0.9f) {
            atomicAdd(&scnt[c], 1);
            atomicAdd(&ssum[c], cm[(3 * c + 2) * HWPIX + p]);
        }
    }
    __syncthreads();

    if (t < NC && scnt[t] > 0) {
        atomicAdd(&g_icnt[t], scnt[t]);
        atomicAdd(&g_dsum[t], ssum[t]);
    }
    __threadfence();
    if (t == 0) s_last = (atomicAdd(&g_done, 1u) == (unsigned)(NBLK - 1));
    __syncthreads();

    if (s_last) {
        __threadfence();
        if (t < NC) {
            const int c = t;
            const unsigned long long best = g_best[c];
            const unsigned cntBest = (unsigned)(best >> 32);
            const unsigned bin     = 0xFFFFFFFFu - (unsigned)best;
            const float cx = (float)(bin % WW);
            const float cy = (float)(bin / WW);
            const bool trig = (g_count[c] >= 500) && (cntBest > 500u);
            const int   icnt = g_icnt[c];
            const float dsum = g_dsum[c];
            const float dmean = (icnt > 0) ? (dsum / (float)icnt)
                                           : __int_as_float(0x7fc00000);
            out[c * 2 + 0]  = trig ? cx    : 0.0f;
            out[c * 2 + 1]  = trig ? cy    : 0.0f;
            out[2 * NC + c] = trig ? dmean : 0.0f;
            g_icnt[c]  = 0;
            g_dsum[c]  = 0.0f;
            g_count[c] = 0;
            g_best[c]  = 0ULL;
        }
        if (t == 0) g_done = 0u;
    }
}

// ---------------- launch ------------------------------------------------------
extern "C" void kernel_launch(void* const* d_in, const int* in_sizes, int n_in,
                              void* d_out, int out_size) {
    const int*   label;
    const float* cm;
    if (in_sizes[0] == HWPIX) {
        label = (const int*)d_in[0];
        cm    = (const float*)d_in[1];
    } else {
        label = (const int*)d_in[1];
        cm    = (const float*)d_in[0];
    }
    float* out = (float*)d_out;

    k1_build<<<NBLK, 256>>>(label, cm);
    k2_vote <<<dim3(WW / NCOL, NC), 256>>>();
    k3_final<<<NBLK, 256>>>(label, cm, out);
}